// round 7
// baseline (speedup 1.0000x reference)
#include <cuda_runtime.h>
#include <cstdint>

// SignedAttention R7: 2 patches per CTA. Shared 80-key window: K staged once,
// V loaded once and used for both patches (zero-padded weights), halved
// barrier/prologue overhead. 5 CTAs/SM.

constexpr int Lv   = 1024;
constexpr int Dv   = 64;
constexpr int NP   = 128;
constexpr int CH   = 8;     // positions per patch
constexpr int NQ   = 16;    // queries per CTA (2 patches)
constexpr int MAXKT= 80;    // union key window
constexpr int KP   = 68;    // K pitch: quad stride 17 -> CF row reads
constexpr int AP   = 17;    // score pitch: gcd(17,32)=1 -> CF scalar access
constexpr int TP   = 84;    // weight pitch: quad stride 21 -> CF quad reads
constexpr int NT   = 256;

__device__ __forceinline__ void cp16(void* dst, const void* src) {
    uint32_t d = (uint32_t)__cvta_generic_to_shared(dst);
    asm volatile("cp.async.cg.shared.global [%0], [%1], 16;" :: "r"(d), "l"(src));
}
__device__ __forceinline__ void cp_commit() { asm volatile("cp.async.commit_group;"); }
__device__ __forceinline__ void cp_wait0()  { asm volatile("cp.async.wait_group 0;"); }

__global__ __launch_bounds__(NT, 5)
void signed_attn_kernel(const float* __restrict__ Q,
                        const float* __restrict__ K,
                        const float* __restrict__ V,
                        const float* __restrict__ LS,
                        float* __restrict__ O)
{
    __shared__ float qs[NQ][Dv];           // 4 KB
    __shared__ float ks[MAXKT][KP];        // 21.3 KB
    __shared__ float at[MAXKT][AP];        // 5.3 KB : scaled-later scores [key][qi]
    __shared__ float at_t[2][CH][TP];      // 5.3 KB : weights [patch][q][key], 0-padded
    __shared__ float part[2][CH][Dv];      // 4 KB   : phase-3 partials
                                           // total ~39.8 KB -> 5 CTAs/SM

    const int bh   = blockIdx.x / (NP / 2);
    const int p0   = (blockIdx.x % (NP / 2)) * 2;       // even patch, <= 126
    const int tid  = threadIdx.x;
    const int warp = tid >> 5;
    const int lane = tid & 31;

    const size_t qbase = ((size_t)bh * Lv + (size_t)p0 * CH) * Dv;       // 16 rows
    const size_t kbase = ((size_t)bh * Lv + (size_t)(p0 + 1) * CH) * Dv; // window base

    const int nk0 = min(9, NP - 1 - p0) * CH;            // patch0 valid keys [0, nk0)
    const int nk1 = min(9, NP - 2 - p0) * CH;            // patch1 valid keys [8, 8+nk1)
    const int nkt = min(10, NP - 1 - p0) * CH;           // staged rows, 8..80 (mult of 8)

    // ---- stage Q (16x64) + K window via cp.async ----
    {
        cp16((float4*)qs + tid, (const float4*)(Q + qbase) + tid);  // 256 quads
        const float4* Kg = (const float4*)(K + kbase);
        const int n4 = nkt * (Dv / 4);
        for (int idx = tid; idx < n4; idx += NT) {
            int r = idx >> 4, c = idx & 15;
            cp16(&ks[r][c * 4], Kg + idx);
        }
        cp_commit();
    }

    const float scale = fminf(fmaxf(expf(LS[0]), 1.0f), 30.0f) * 0.125f;

    cp_wait0();
    __syncthreads();

    // ---- phase 1: 3 warps, lane = key j; two 8-query passes (acc[8]) ----
    if (warp < 3) {
        const int j = warp * 32 + lane;
        if (j < nkt) {
            #pragma unroll
            for (int gp = 0; gp < 2; gp++) {
                float acc[CH] = {0,0,0,0,0,0,0,0};
                #pragma unroll
                for (int dd = 0; dd < Dv / 4; dd++) {
                    const float4 kf = *(const float4*)&ks[j][dd * 4];
                    #pragma unroll
                    for (int qi = 0; qi < CH; qi++) {
                        const float4 qf = *(const float4*)&qs[gp * CH + qi][dd * 4];
                        acc[qi] = fmaf(qf.x, kf.x, acc[qi]);
                        acc[qi] = fmaf(qf.y, kf.y, acc[qi]);
                        acc[qi] = fmaf(qf.z, kf.z, acc[qi]);
                        acc[qi] = fmaf(qf.w, kf.w, acc[qi]);
                    }
                }
                #pragma unroll
                for (int qi = 0; qi < CH; qi++)
                    at[j][gp * CH + qi] = acc[qi];       // pitch-17: CF
            }
        }
    }
    __syncthreads();

    // ---- phase 2: warp = q; dual softmax for (patch0,q) and (patch1,q) ----
    {
        const int q = warp;
        #pragma unroll
        for (int pt = 0; pt < 2; pt++) {
            const int col = pt * CH + q;
            const int lo  = pt * CH;                     // patch1 keys start at 8
            const int hi  = lo + (pt ? nk1 : nk0);
            float t[3]; bool v[3];
            float mx = -1e30f, mn = 1e30f;
            #pragma unroll
            for (int s = 0; s < 3; s++) {
                const int j = lane + s * 32;
                v[s] = (j >= lo) && (j < hi);
                t[s] = v[s] ? at[j][col] * scale : 0.0f;
                if (v[s]) { mx = fmaxf(mx, t[s]); mn = fminf(mn, t[s]); }
            }
            #pragma unroll
            for (int o = 16; o; o >>= 1) {
                mx = fmaxf(mx, __shfl_xor_sync(0xffffffffu, mx, o));
                mn = fminf(mn, __shfl_xor_sync(0xffffffffu, mn, o));
            }
            float sp = 0.0f, sn = 0.0f, ep[3], en[3];
            #pragma unroll
            for (int s = 0; s < 3; s++) {
                ep[s] = en[s] = 0.0f;
                if (v[s]) {
                    ep[s] = __expf(t[s] - mx);
                    en[s] = __expf(mn - t[s]);
                    sp += ep[s]; sn += en[s];
                }
            }
            #pragma unroll
            for (int o = 16; o; o >>= 1) {
                sp += __shfl_xor_sync(0xffffffffu, sp, o);
                sn += __shfl_xor_sync(0xffffffffu, sn, o);
            }
            const float rp = 1.0f / sp;
            const float rn = 1.0f / sn;
            #pragma unroll
            for (int s = 0; s < 3; s++) {
                const int j = lane + s * 32;
                if (j < nkt)
                    at_t[pt][q][j] = v[s] ? (ep[s] * rp - en[s] * rn) : 0.0f;
            }
        }
    }
    __syncthreads();

    // ---- phase 3: key-halves x 16-wide d-slices; V LDG shared by 2 patches ----
    {
        const int w4   = warp & 3;
        const int q    = lane >> 2;                      // 0..7
        const int dof  = w4 * 16 + (lane & 3) * 4;       // float4 slice
        const int half = nkt >> 1;                       // multiple of 4
        const int j0   = (warp >= 4) ? half : 0;
        const int j1   = j0 + half;

        const float* __restrict__ Vrow = V + kbase + dof;

        float4 a0 = make_float4(0.f, 0.f, 0.f, 0.f);
        float4 a1 = make_float4(0.f, 0.f, 0.f, 0.f);
        for (int j = j0; j < j1; j += 4) {
            const float4 w0 = *(const float4*)&at_t[0][q][j];   // CF quad
            const float4 w1 = *(const float4*)&at_t[1][q][j];
            float4 vv;
            vv = *(const float4*)(Vrow + (size_t)(j + 0) * Dv);
            a0.x = fmaf(w0.x, vv.x, a0.x); a0.y = fmaf(w0.x, vv.y, a0.y);
            a0.z = fmaf(w0.x, vv.z, a0.z); a0.w = fmaf(w0.x, vv.w, a0.w);
            a1.x = fmaf(w1.x, vv.x, a1.x); a1.y = fmaf(w1.x, vv.y, a1.y);
            a1.z = fmaf(w1.x, vv.z, a1.z); a1.w = fmaf(w1.x, vv.w, a1.w);
            vv = *(const float4*)(Vrow + (size_t)(j + 1) * Dv);
            a0.x = fmaf(w0.y, vv.x, a0.x); a0.y = fmaf(w0.y, vv.y, a0.y);
            a0.z = fmaf(w0.y, vv.z, a0.z); a0.w = fmaf(w0.y, vv.w, a0.w);
            a1.x = fmaf(w1.y, vv.x, a1.x); a1.y = fmaf(w1.y, vv.y, a1.y);
            a1.z = fmaf(w1.y, vv.z, a1.z); a1.w = fmaf(w1.y, vv.w, a1.w);
            vv = *(const float4*)(Vrow + (size_t)(j + 2) * Dv);
            a0.x = fmaf(w0.z, vv.x, a0.x); a0.y = fmaf(w0.z, vv.y, a0.y);
            a0.z = fmaf(w0.z, vv.z, a0.z); a0.w = fmaf(w0.z, vv.w, a0.w);
            a1.x = fmaf(w1.z, vv.x, a1.x); a1.y = fmaf(w1.z, vv.y, a1.y);
            a1.z = fmaf(w1.z, vv.z, a1.z); a1.w = fmaf(w1.z, vv.w, a1.w);
            vv = *(const float4*)(Vrow + (size_t)(j + 3) * Dv);
            a0.x = fmaf(w0.w, vv.x, a0.x); a0.y = fmaf(w0.w, vv.y, a0.y);
            a0.z = fmaf(w0.w, vv.z, a0.z); a0.w = fmaf(w0.w, vv.w, a0.w);
            a1.x = fmaf(w1.w, vv.x, a1.x); a1.y = fmaf(w1.w, vv.y, a1.y);
            a1.z = fmaf(w1.w, vv.z, a1.z); a1.w = fmaf(w1.w, vv.w, a1.w);
        }
        if (warp >= 4) {
            *(float4*)&part[0][q][dof] = a0;
            *(float4*)&part[1][q][dof] = a1;
        }
        __syncthreads();
        if (warp < 4) {
            const float4 p0v = *(const float4*)&part[0][q][dof];
            const float4 p1v = *(const float4*)&part[1][q][dof];
            a0.x += p0v.x; a0.y += p0v.y; a0.z += p0v.z; a0.w += p0v.w;
            a1.x += p1v.x; a1.y += p1v.y; a1.z += p1v.z; a1.w += p1v.w;
            *(float4*)(O + qbase + (size_t)q * Dv + dof)        = a0;
            *(float4*)(O + qbase + (size_t)(CH + q) * Dv + dof) = a1;
        }
    }
}

extern "C" void kernel_launch(void* const* d_in, const int* in_sizes, int n_in,
                              void* d_out, int out_size)
{
    const float* Q  = (const float*)d_in[0];
    const float* K  = (const float*)d_in[1];
    const float* V  = (const float*)d_in[2];
    const float* LS = (const float*)d_in[3];
    float* O = (float*)d_out;

    const int BH = in_sizes[0] / (Lv * Dv);   // B*H = 32
    signed_attn_kernel<<<BH * (NP / 2), NT>>>(Q, K, V, LS, O);
}

// round 9
// speedup vs baseline: 1.5776x; 1.5776x over previous
#include <cuda_runtime.h>
#include <cstdint>

// SignedAttention R8: revert to R6 shape (1 patch/CTA, V direct LDG).
// + 6 CTAs/SM (reg budget 42), + 6-warp d-split phase 1.

constexpr int Lv   = 1024;
constexpr int Dv   = 64;
constexpr int NP   = 128;
constexpr int CH   = 8;
constexpr int MAXK = 72;
constexpr int KP   = 76;   // K pitch: quad stride 19 -> CF row reads
constexpr int AP   = 9;    // score pitch: gcd(9,32)=1 -> CF scalar access
constexpr int TP   = 76;   // at_t pitch: 19q mod 32 distinct -> CF quad reads
constexpr int NT   = 256;

__device__ __forceinline__ void cp16(void* dst, const void* src) {
    uint32_t d = (uint32_t)__cvta_generic_to_shared(dst);
    asm volatile("cp.async.cg.shared.global [%0], [%1], 16;" :: "r"(d), "l"(src));
}
__device__ __forceinline__ void cp_commit() { asm volatile("cp.async.commit_group;"); }
__device__ __forceinline__ void cp_wait0()  { asm volatile("cp.async.wait_group 0;"); }

__global__ __launch_bounds__(NT, 6)
void signed_attn_kernel(const float* __restrict__ Q,
                        const float* __restrict__ K,
                        const float* __restrict__ V,
                        const float* __restrict__ LS,
                        float* __restrict__ O)
{
    __shared__ float qs[CH][Dv];           // 2 KB
    __shared__ float ks[MAXK][KP];         // 21.4 KB
    __shared__ float at2[2][MAXK][AP];     // 5.1 KB : raw score halves [h][key][q]
    __shared__ float at_t[CH][TP];         // 2.4 KB : weights [q][key]
    __shared__ float part[CH][Dv];         // 2 KB  : phase-3 partials
                                           // total ~32.9 KB -> 6 CTAs/SM

    const int bh   = blockIdx.x / NP;
    const int p    = blockIdx.x % NP;
    const int tid  = threadIdx.x;
    const int warp = tid >> 5;
    const int lane = tid & 31;

    const size_t qbase = ((size_t)bh * Lv + (size_t)p * CH) * Dv;

    const int npk = min(9, NP - 1 - p);
    const int nk  = npk * CH;              // multiple of 8, 0..72

    if (nk == 0) {                         // last patch: A == 0 exactly
        O[qbase + tid]      = 0.0f;
        O[qbase + tid + NT] = 0.0f;
        return;
    }

    // ---- stage Q + K via cp.async (V is NOT staged) ----
    const size_t kbase = ((size_t)bh * Lv + (size_t)(p + 1) * CH) * Dv;
    const int n4 = nk * (Dv / 4);
    {
        if (tid < (CH * Dv) / 4) {
            int r = tid >> 4, c = tid & 15;
            cp16(&qs[r][c * 4], (const float4*)(Q + qbase) + tid);
        }
        const float4* Kg = (const float4*)(K + kbase);
        for (int idx = tid; idx < n4; idx += NT) {
            int r = idx >> 4, c = idx & 15;
            cp16(&ks[r][c * 4], Kg + idx);
        }
        cp_commit();
    }

    const float scale = fminf(fmaxf(expf(LS[0]), 1.0f), 30.0f) * 0.125f;

    cp_wait0();
    __syncthreads();

    // ---- phase 1: 6 warps = (3 key-groups) x (2 d-halves); acc over 8 q ----
    if (warp < 6) {
        const int h = (warp >= 3) ? 1 : 0;             // d-half
        const int j = (warp - 3 * h) * 32 + lane;      // key
        if (j < nk) {
            const int db = h * 8;                      // 8 quads = 32 dims
            float acc[CH] = {0,0,0,0,0,0,0,0};
            #pragma unroll
            for (int dd = 0; dd < 8; dd++) {
                const int c = (db + dd) * 4;
                const float4 kf = *(const float4*)&ks[j][c];
                #pragma unroll
                for (int qi = 0; qi < CH; qi++) {
                    const float4 qf = *(const float4*)&qs[qi][c];
                    acc[qi] = fmaf(qf.x, kf.x, acc[qi]);
                    acc[qi] = fmaf(qf.y, kf.y, acc[qi]);
                    acc[qi] = fmaf(qf.z, kf.z, acc[qi]);
                    acc[qi] = fmaf(qf.w, kf.w, acc[qi]);
                }
            }
            #pragma unroll
            for (int qi = 0; qi < CH; qi++)
                at2[h][j][qi] = acc[qi];               // pitch-9: CF
        }
    }
    __syncthreads();

    // ---- phase 2: warp q -> dual softmax (adds d-halves); write transposed ----
    {
        const int q = warp;
        const bool v0 = (lane      < nk);
        const bool v1 = (lane + 32 < nk);
        const bool v2 = (lane + 64 < nk);
        const float t0 = v0 ? (at2[0][lane     ][q] + at2[1][lane     ][q]) * scale : 0.0f;
        const float t1 = v1 ? (at2[0][lane + 32][q] + at2[1][lane + 32][q]) * scale : 0.0f;
        const float t2 = v2 ? (at2[0][lane + 64][q] + at2[1][lane + 64][q]) * scale : 0.0f;

        float mx = -1e30f, mn = 1e30f;
        if (v0) { mx = fmaxf(mx, t0); mn = fminf(mn, t0); }
        if (v1) { mx = fmaxf(mx, t1); mn = fminf(mn, t1); }
        if (v2) { mx = fmaxf(mx, t2); mn = fminf(mn, t2); }
        #pragma unroll
        for (int o = 16; o; o >>= 1) {
            mx = fmaxf(mx, __shfl_xor_sync(0xffffffffu, mx, o));
            mn = fminf(mn, __shfl_xor_sync(0xffffffffu, mn, o));
        }

        float sp = 0.0f, sn = 0.0f;
        float e0p=0, e0n=0, e1p=0, e1n=0, e2p=0, e2n=0;
        if (v0) { e0p = __expf(t0 - mx); e0n = __expf(mn - t0); sp += e0p; sn += e0n; }
        if (v1) { e1p = __expf(t1 - mx); e1n = __expf(mn - t1); sp += e1p; sn += e1n; }
        if (v2) { e2p = __expf(t2 - mx); e2n = __expf(mn - t2); sp += e2p; sn += e2n; }
        #pragma unroll
        for (int o = 16; o; o >>= 1) {
            sp += __shfl_xor_sync(0xffffffffu, sp, o);
            sn += __shfl_xor_sync(0xffffffffu, sn, o);
        }
        const float rp = 1.0f / sp;
        const float rn = 1.0f / sn;
        if (v0) at_t[q][lane     ] = e0p * rp - e0n * rn;
        if (v1) at_t[q][lane + 32] = e1p * rp - e1n * rn;
        if (v2) at_t[q][lane + 64] = e2p * rp - e2n * rn;
    }
    __syncthreads();

    // ---- phase 3: key-halves x 16-wide d-slices; V via direct LDG.128 ----
    {
        const int w4   = warp & 3;
        const int q    = lane >> 2;                     // 0..7
        const int dof  = w4 * 16 + (lane & 3) * 4;      // float4 slice
        const int half = nk >> 1;                       // multiple of 4
        const int j0   = (warp >= 4) ? half : 0;
        const int j1   = j0 + half;

        const float4* __restrict__ Vg =
            (const float4*)(V + kbase + dof) + (size_t)j0 * (Dv / 4);

        float4 acc = make_float4(0.f, 0.f, 0.f, 0.f);
        #pragma unroll 4
        for (int j = j0; j < j1; j += 4) {
            const float4 a4 = *(const float4*)&at_t[q][j];   // CF quad read
            float4 vv;
            vv = Vg[0 * (Dv / 4)];
            acc.x = fmaf(a4.x, vv.x, acc.x); acc.y = fmaf(a4.x, vv.y, acc.y);
            acc.z = fmaf(a4.x, vv.z, acc.z); acc.w = fmaf(a4.x, vv.w, acc.w);
            vv = Vg[1 * (Dv / 4)];
            acc.x = fmaf(a4.y, vv.x, acc.x); acc.y = fmaf(a4.y, vv.y, acc.y);
            acc.z = fmaf(a4.y, vv.z, acc.z); acc.w = fmaf(a4.y, vv.w, acc.w);
            vv = Vg[2 * (Dv / 4)];
            acc.x = fmaf(a4.z, vv.x, acc.x); acc.y = fmaf(a4.z, vv.y, acc.y);
            acc.z = fmaf(a4.z, vv.z, acc.z); acc.w = fmaf(a4.z, vv.w, acc.w);
            vv = Vg[3 * (Dv / 4)];
            acc.x = fmaf(a4.w, vv.x, acc.x); acc.y = fmaf(a4.w, vv.y, acc.y);
            acc.z = fmaf(a4.w, vv.z, acc.z); acc.w = fmaf(a4.w, vv.w, acc.w);
            Vg += 4 * (Dv / 4);
        }
        if (warp >= 4)
            *(float4*)&part[q][dof] = acc;
        __syncthreads();
        if (warp < 4) {
            const float4 pp = *(const float4*)&part[q][dof];
            acc.x += pp.x; acc.y += pp.y; acc.z += pp.z; acc.w += pp.w;
            *(float4*)(O + qbase + (size_t)q * Dv + dof) = acc;
        }
    }
}

extern "C" void kernel_launch(void* const* d_in, const int* in_sizes, int n_in,
                              void* d_out, int out_size)
{
    const float* Q  = (const float*)d_in[0];
    const float* K  = (const float*)d_in[1];
    const float* V  = (const float*)d_in[2];
    const float* LS = (const float*)d_in[3];
    float* O = (float*)d_out;

    const int BH = in_sizes[0] / (Lv * Dv);   // B*H = 32
    signed_attn_kernel<<<BH * NP, NT>>>(Q, K, V, LS, O);
}

// round 10
// speedup vs baseline: 1.6588x; 1.0515x over previous
#include <cuda_runtime.h>
#include <cstdint>

// SignedAttention R9: R8 dataflow + packed f32x2 FMA (FFMA2) in phases 1 & 3.
// 1 patch/CTA, Q+K staged via cp.async, V direct LDG, 6-warp d-split phase 1.

constexpr int Lv   = 1024;
constexpr int Dv   = 64;
constexpr int NP   = 128;
constexpr int CH   = 8;
constexpr int MAXK = 72;
constexpr int KP   = 76;   // K pitch: quad stride 19 -> CF row reads
constexpr int AP   = 9;    // score pitch: gcd(9,32)=1 -> CF scalar access
constexpr int TP   = 76;   // at_t pitch: 19q mod 32 distinct -> CF quad reads
constexpr int NT   = 256;

using u64 = unsigned long long;

__device__ __forceinline__ void cp16(void* dst, const void* src) {
    uint32_t d = (uint32_t)__cvta_generic_to_shared(dst);
    asm volatile("cp.async.cg.shared.global [%0], [%1], 16;" :: "r"(d), "l"(src));
}
__device__ __forceinline__ void cp_commit() { asm volatile("cp.async.commit_group;"); }
__device__ __forceinline__ void cp_wait0()  { asm volatile("cp.async.wait_group 0;"); }

__device__ __forceinline__ u64 pack2(float lo, float hi) {
    u64 r; asm("mov.b64 %0, {%1, %2};" : "=l"(r) : "f"(lo), "f"(hi)); return r;
}
__device__ __forceinline__ void ffma2(u64& acc, u64 a, u64 b) {
    asm("fma.rn.f32x2 %0, %1, %2, %0;" : "+l"(acc) : "l"(a), "l"(b));
}
__device__ __forceinline__ float2 unpack2(u64 v) {
    float lo, hi; asm("mov.b64 {%0, %1}, %2;" : "=f"(lo), "=f"(hi) : "l"(v));
    return make_float2(lo, hi);
}

__global__ __launch_bounds__(NT, 5)
void signed_attn_kernel(const float* __restrict__ Q,
                        const float* __restrict__ K,
                        const float* __restrict__ V,
                        const float* __restrict__ LS,
                        float* __restrict__ O)
{
    __shared__ float qs[CH][Dv];           // 2 KB
    __shared__ float ks[MAXK][KP];         // 21.4 KB
    __shared__ float at2[2][MAXK][AP];     // 5.1 KB : raw score halves [h][key][q]
    __shared__ float at_t[CH][TP];         // 2.4 KB : weights [q][key]
    __shared__ float part[CH][Dv];         // 2 KB  : phase-3 partials

    const int bh   = blockIdx.x / NP;
    const int p    = blockIdx.x % NP;
    const int tid  = threadIdx.x;
    const int warp = tid >> 5;
    const int lane = tid & 31;

    const size_t qbase = ((size_t)bh * Lv + (size_t)p * CH) * Dv;

    const int npk = min(9, NP - 1 - p);
    const int nk  = npk * CH;              // multiple of 8, 0..72

    if (nk == 0) {                         // last patch: A == 0 exactly
        O[qbase + tid]      = 0.0f;
        O[qbase + tid + NT] = 0.0f;
        return;
    }

    // ---- stage Q + K via cp.async (V is NOT staged) ----
    const size_t kbase = ((size_t)bh * Lv + (size_t)(p + 1) * CH) * Dv;
    const int n4 = nk * (Dv / 4);
    {
        if (tid < (CH * Dv) / 4) {
            int r = tid >> 4, c = tid & 15;
            cp16(&qs[r][c * 4], (const float4*)(Q + qbase) + tid);
        }
        const float4* Kg = (const float4*)(K + kbase);
        for (int idx = tid; idx < n4; idx += NT) {
            int r = idx >> 4, c = idx & 15;
            cp16(&ks[r][c * 4], Kg + idx);
        }
        cp_commit();
    }

    const float scale = fminf(fmaxf(expf(LS[0]), 1.0f), 30.0f) * 0.125f;

    cp_wait0();
    __syncthreads();

    // ---- phase 1: 6 warps = (3 key-groups) x (2 d-halves); FFMA2, 8 q accs ----
    if (warp < 6) {
        const int h = (warp >= 3) ? 1 : 0;             // d-half
        const int j = (warp - 3 * h) * 32 + lane;      // key
        if (j < nk) {
            const int db = h * 8;                      // 8 quads = 32 dims
            u64 acc[CH] = {0,0,0,0,0,0,0,0};           // packed (even-d, odd-d)
            #pragma unroll
            for (int dd = 0; dd < 8; dd++) {
                const int c = (db + dd) * 4;
                const float4 kf = *(const float4*)&ks[j][c];
                const u64 k01 = pack2(kf.x, kf.y);
                const u64 k23 = pack2(kf.z, kf.w);
                #pragma unroll
                for (int qi = 0; qi < CH; qi++) {
                    const float4 qf = *(const float4*)&qs[qi][c];
                    ffma2(acc[qi], pack2(qf.x, qf.y), k01);
                    ffma2(acc[qi], pack2(qf.z, qf.w), k23);
                }
            }
            #pragma unroll
            for (int qi = 0; qi < CH; qi++) {
                const float2 s = unpack2(acc[qi]);
                at2[h][j][qi] = s.x + s.y;             // pitch-9: CF
            }
        }
    }
    __syncthreads();

    // ---- phase 2: warp q -> dual softmax (adds d-halves); write transposed ----
    {
        const int q = warp;
        const bool v0 = (lane      < nk);
        const bool v1 = (lane + 32 < nk);
        const bool v2 = (lane + 64 < nk);
        const float t0 = v0 ? (at2[0][lane     ][q] + at2[1][lane     ][q]) * scale : 0.0f;
        const float t1 = v1 ? (at2[0][lane + 32][q] + at2[1][lane + 32][q]) * scale : 0.0f;
        const float t2 = v2 ? (at2[0][lane + 64][q] + at2[1][lane + 64][q]) * scale : 0.0f;

        float mx = -1e30f, mn = 1e30f;
        if (v0) { mx = fmaxf(mx, t0); mn = fminf(mn, t0); }
        if (v1) { mx = fmaxf(mx, t1); mn = fminf(mn, t1); }
        if (v2) { mx = fmaxf(mx, t2); mn = fminf(mn, t2); }
        #pragma unroll
        for (int o = 16; o; o >>= 1) {
            mx = fmaxf(mx, __shfl_xor_sync(0xffffffffu, mx, o));
            mn = fminf(mn, __shfl_xor_sync(0xffffffffu, mn, o));
        }

        float sp = 0.0f, sn = 0.0f;
        float e0p=0, e0n=0, e1p=0, e1n=0, e2p=0, e2n=0;
        if (v0) { e0p = __expf(t0 - mx); e0n = __expf(mn - t0); sp += e0p; sn += e0n; }
        if (v1) { e1p = __expf(t1 - mx); e1n = __expf(mn - t1); sp += e1p; sn += e1n; }
        if (v2) { e2p = __expf(t2 - mx); e2n = __expf(mn - t2); sp += e2p; sn += e2n; }
        #pragma unroll
        for (int o = 16; o; o >>= 1) {
            sp += __shfl_xor_sync(0xffffffffu, sp, o);
            sn += __shfl_xor_sync(0xffffffffu, sn, o);
        }
        const float rp = 1.0f / sp;
        const float rn = 1.0f / sn;
        if (v0) at_t[q][lane     ] = e0p * rp - e0n * rn;
        if (v1) at_t[q][lane + 32] = e1p * rp - e1n * rn;
        if (v2) at_t[q][lane + 64] = e2p * rp - e2n * rn;
    }
    __syncthreads();

    // ---- phase 3: key-halves x 16-wide d-slices; V direct LDG, FFMA2 ----
    {
        const int w4   = warp & 3;
        const int q    = lane >> 2;                     // 0..7
        const int dof  = w4 * 16 + (lane & 3) * 4;      // float4 slice
        const int half = nk >> 1;                       // multiple of 4
        const int j0   = (warp >= 4) ? half : 0;
        const int j1   = j0 + half;

        const float4* __restrict__ Vg =
            (const float4*)(V + kbase + dof) + (size_t)j0 * (Dv / 4);

        u64 a01 = 0, a23 = 0;                           // packed d-pair accs
        #pragma unroll 4
        for (int j = j0; j < j1; j += 4) {
            const float4 a4 = *(const float4*)&at_t[q][j];   // CF quad read
            float4 vv; u64 aa;
            vv = Vg[0 * (Dv / 4)]; aa = pack2(a4.x, a4.x);
            ffma2(a01, pack2(vv.x, vv.y), aa);
            ffma2(a23, pack2(vv.z, vv.w), aa);
            vv = Vg[1 * (Dv / 4)]; aa = pack2(a4.y, a4.y);
            ffma2(a01, pack2(vv.x, vv.y), aa);
            ffma2(a23, pack2(vv.z, vv.w), aa);
            vv = Vg[2 * (Dv / 4)]; aa = pack2(a4.z, a4.z);
            ffma2(a01, pack2(vv.x, vv.y), aa);
            ffma2(a23, pack2(vv.z, vv.w), aa);
            vv = Vg[3 * (Dv / 4)]; aa = pack2(a4.w, a4.w);
            ffma2(a01, pack2(vv.x, vv.y), aa);
            ffma2(a23, pack2(vv.z, vv.w), aa);
            Vg += 4 * (Dv / 4);
        }
        const float2 e01 = unpack2(a01);
        const float2 e23 = unpack2(a23);
        float4 acc = make_float4(e01.x, e01.y, e23.x, e23.y);

        if (warp >= 4)
            *(float4*)&part[q][dof] = acc;
        __syncthreads();
        if (warp < 4) {
            const float4 pp = *(const float4*)&part[q][dof];
            acc.x += pp.x; acc.y += pp.y; acc.z += pp.z; acc.w += pp.w;
            *(float4*)(O + qbase + (size_t)q * Dv + dof) = acc;
        }
    }
}

extern "C" void kernel_launch(void* const* d_in, const int* in_sizes, int n_in,
                              void* d_out, int out_size)
{
    const float* Q  = (const float*)d_in[0];
    const float* K  = (const float*)d_in[1];
    const float* V  = (const float*)d_in[2];
    const float* LS = (const float*)d_in[3];
    float* O = (float*)d_out;

    const int BH = in_sizes[0] / (Lv * Dv);   // B*H = 32
    signed_attn_kernel<<<BH * NP, NT>>>(Q, K, V, LS, O);
}